// round 3
// baseline (speedup 1.0000x reference)
#include <cuda_runtime.h>
#include <cstdint>

// PPRGo: out[n,:] = sum_k ( mask(wei[n,k]) / (sum_k mask + 1e-12) ) * emb_table[nei[n,k], :]
// N=200000, TOPK=32, EMB=64. nei is int32 on the wire.
//
// One warp per node. Gather loads use ld.global.cg (L2-only): emb_table rows
// have ~0% L1 hit rate (51MB table, random indices, 228KB L1), so L1 fills
// are pure overhead — R2 ncu showed l1tex at 86.8% (≈half of it fill traffic).
// Streaming inputs (wei/nei) and the output use evict-first (.cs) hints.

static constexpr int TOPK = 32;
static constexpr int EMB  = 64;

__global__ __launch_bounds__(256)
void pprgo_kernel(const float* __restrict__ emb,   // [N, 64]
                  const float* __restrict__ wei,   // [N, 32]
                  const int*   __restrict__ nei,   // [N, 32] int32
                  float* __restrict__ out,         // [N, 64]
                  int n_nodes)
{
    const int warp_id = (blockIdx.x * blockDim.x + threadIdx.x) >> 5;
    const int lane    = threadIdx.x & 31;
    if (warp_id >= n_nodes) return;

    const size_t row = (size_t)warp_id * TOPK;

    // --- weight phase: lane k handles neighbor k (streaming reads) ---
    float w  = __ldcs(wei + row + lane);
    float m  = (w != 0.0f) ? 1.0f : 0.0f;
    float s  = m;
    #pragma unroll
    for (int o = 16; o > 0; o >>= 1)
        s += __shfl_xor_sync(0xFFFFFFFFu, s, o);
    const float myw = m * (1.0f / (s + 1e-12f));

    const int myidx = __ldcs(nei + row + lane);

    // --- gather phase: lane owns float2 slice [2*lane, 2*lane+1] of EMB ---
    const float2* __restrict__ e2 = reinterpret_cast<const float2*>(emb);

    float accx = 0.0f, accy = 0.0f;

    #pragma unroll
    for (int k = 0; k < TOPK; k += 8) {
        int i0 = __shfl_sync(0xFFFFFFFFu, myidx, k + 0);
        int i1 = __shfl_sync(0xFFFFFFFFu, myidx, k + 1);
        int i2 = __shfl_sync(0xFFFFFFFFu, myidx, k + 2);
        int i3 = __shfl_sync(0xFFFFFFFFu, myidx, k + 3);
        int i4 = __shfl_sync(0xFFFFFFFFu, myidx, k + 4);
        int i5 = __shfl_sync(0xFFFFFFFFu, myidx, k + 5);
        int i6 = __shfl_sync(0xFFFFFFFFu, myidx, k + 6);
        int i7 = __shfl_sync(0xFFFFFFFFu, myidx, k + 7);

        float w0 = __shfl_sync(0xFFFFFFFFu, myw, k + 0);
        float w1 = __shfl_sync(0xFFFFFFFFu, myw, k + 1);
        float w2 = __shfl_sync(0xFFFFFFFFu, myw, k + 2);
        float w3 = __shfl_sync(0xFFFFFFFFu, myw, k + 3);
        float w4 = __shfl_sync(0xFFFFFFFFu, myw, k + 4);
        float w5 = __shfl_sync(0xFFFFFFFFu, myw, k + 5);
        float w6 = __shfl_sync(0xFFFFFFFFu, myw, k + 6);
        float w7 = __shfl_sync(0xFFFFFFFFu, myw, k + 7);

        // 8 independent L2-only loads in flight per warp
        float2 v0 = __ldcg(e2 + (size_t)i0 * (EMB/2) + lane);
        float2 v1 = __ldcg(e2 + (size_t)i1 * (EMB/2) + lane);
        float2 v2 = __ldcg(e2 + (size_t)i2 * (EMB/2) + lane);
        float2 v3 = __ldcg(e2 + (size_t)i3 * (EMB/2) + lane);
        float2 v4 = __ldcg(e2 + (size_t)i4 * (EMB/2) + lane);
        float2 v5 = __ldcg(e2 + (size_t)i5 * (EMB/2) + lane);
        float2 v6 = __ldcg(e2 + (size_t)i6 * (EMB/2) + lane);
        float2 v7 = __ldcg(e2 + (size_t)i7 * (EMB/2) + lane);

        accx += w0 * v0.x; accy += w0 * v0.y;
        accx += w1 * v1.x; accy += w1 * v1.y;
        accx += w2 * v2.x; accy += w2 * v2.y;
        accx += w3 * v3.x; accy += w3 * v3.y;
        accx += w4 * v4.x; accy += w4 * v4.y;
        accx += w5 * v5.x; accy += w5 * v5.y;
        accx += w6 * v6.x; accy += w6 * v6.y;
        accx += w7 * v7.x; accy += w7 * v7.y;
    }

    float2* __restrict__ o2 = reinterpret_cast<float2*>(out);
    __stcs(o2 + (size_t)warp_id * (EMB/2) + lane, make_float2(accx, accy));
}

extern "C" void kernel_launch(void* const* d_in, const int* in_sizes, int n_in,
                              void* d_out, int out_size)
{
    const float* emb = (const float*)d_in[0];   // [N, 64]
    const float* wei = (const float*)d_in[1];   // [N, 32]
    const int*   nei = (const int*)d_in[2];     // [N, 32] int32
    float*       out = (float*)d_out;           // [N, 1, 64]

    const int n_nodes = in_sizes[1] / TOPK;     // 200000

    const int threads = 256;                    // 8 warps/block
    const int warps_per_block = threads / 32;
    const int blocks = (n_nodes + warps_per_block - 1) / warps_per_block;

    pprgo_kernel<<<blocks, threads>>>(emb, wei, nei, out, n_nodes);
}

// round 4
// speedup vs baseline: 1.2453x; 1.2453x over previous
#include <cuda_runtime.h>
#include <cstdint>

// PPRGo: out[n,:] = sum_k ( mask(wei[n,k]) / (sum_k mask + 1e-12) ) * emb_table[nei[n,k], :]
// N=200000, TOPK=32, EMB=64. nei is int32 on the wire.
//
// One warp per node. Gather uses LDG.128 with TWO neighbor rows per
// instruction: lanes 0-15 cover row 2j, lanes 16-31 cover row 2j+1
// (16 lanes x float4 = 256 B = one row). This halves gather instruction
// and shuffle counts vs the R2 float2 version while keeping the same
// (compulsory) L1 wavefront traffic. Final shfl_xor(16) merges the two
// half-warp partial sums. Plain LDG (R3 showed cache hints regress).

static constexpr int TOPK = 32;
static constexpr int EMB  = 64;

__global__ __launch_bounds__(256)
void pprgo_kernel(const float* __restrict__ emb,   // [N, 64]
                  const float* __restrict__ wei,   // [N, 32]
                  const int*   __restrict__ nei,   // [N, 32] int32
                  float* __restrict__ out,         // [N, 64]
                  int n_nodes)
{
    const int warp_id = (blockIdx.x * blockDim.x + threadIdx.x) >> 5;
    const int lane    = threadIdx.x & 31;
    if (warp_id >= n_nodes) return;

    const size_t row = (size_t)warp_id * TOPK;

    // --- weight phase: lane k handles neighbor k ---
    float w  = wei[row + lane];
    float m  = (w != 0.0f) ? 1.0f : 0.0f;
    float s  = m;
    #pragma unroll
    for (int o = 16; o > 0; o >>= 1)
        s += __shfl_xor_sync(0xFFFFFFFFu, s, o);
    const float myw = m * (1.0f / (s + 1e-12f));

    const int myidx = nei[row + lane];

    // --- gather phase: half-warp h owns row 2j+h; lane covers 4 floats ---
    const int half = lane >> 4;          // 0 or 1
    const int hl   = lane & 15;          // position within half-warp

    const float4* __restrict__ e4 = reinterpret_cast<const float4*>(emb);

    float4 acc = make_float4(0.f, 0.f, 0.f, 0.f);

    #pragma unroll
    for (int j = 0; j < TOPK / 2; j += 8) {
        int src0 = 2 * (j + 0) + half;
        int src1 = 2 * (j + 1) + half;
        int src2 = 2 * (j + 2) + half;
        int src3 = 2 * (j + 3) + half;
        int src4 = 2 * (j + 4) + half;
        int src5 = 2 * (j + 5) + half;
        int src6 = 2 * (j + 6) + half;
        int src7 = 2 * (j + 7) + half;

        int i0 = __shfl_sync(0xFFFFFFFFu, myidx, src0);
        int i1 = __shfl_sync(0xFFFFFFFFu, myidx, src1);
        int i2 = __shfl_sync(0xFFFFFFFFu, myidx, src2);
        int i3 = __shfl_sync(0xFFFFFFFFu, myidx, src3);
        int i4 = __shfl_sync(0xFFFFFFFFu, myidx, src4);
        int i5 = __shfl_sync(0xFFFFFFFFu, myidx, src5);
        int i6 = __shfl_sync(0xFFFFFFFFu, myidx, src6);
        int i7 = __shfl_sync(0xFFFFFFFFu, myidx, src7);

        float w0 = __shfl_sync(0xFFFFFFFFu, myw, src0);
        float w1 = __shfl_sync(0xFFFFFFFFu, myw, src1);
        float w2 = __shfl_sync(0xFFFFFFFFu, myw, src2);
        float w3 = __shfl_sync(0xFFFFFFFFu, myw, src3);
        float w4 = __shfl_sync(0xFFFFFFFFu, myw, src4);
        float w5 = __shfl_sync(0xFFFFFFFFu, myw, src5);
        float w6 = __shfl_sync(0xFFFFFFFFu, myw, src6);
        float w7 = __shfl_sync(0xFFFFFFFFu, myw, src7);

        // 8 independent LDG.128 in flight; each covers 2 neighbor rows
        float4 v0 = e4[(size_t)i0 * (EMB/4) + hl];
        float4 v1 = e4[(size_t)i1 * (EMB/4) + hl];
        float4 v2 = e4[(size_t)i2 * (EMB/4) + hl];
        float4 v3 = e4[(size_t)i3 * (EMB/4) + hl];
        float4 v4 = e4[(size_t)i4 * (EMB/4) + hl];
        float4 v5 = e4[(size_t)i5 * (EMB/4) + hl];
        float4 v6 = e4[(size_t)i6 * (EMB/4) + hl];
        float4 v7 = e4[(size_t)i7 * (EMB/4) + hl];

        acc.x += w0 * v0.x; acc.y += w0 * v0.y; acc.z += w0 * v0.z; acc.w += w0 * v0.w;
        acc.x += w1 * v1.x; acc.y += w1 * v1.y; acc.z += w1 * v1.z; acc.w += w1 * v1.w;
        acc.x += w2 * v2.x; acc.y += w2 * v2.y; acc.z += w2 * v2.z; acc.w += w2 * v2.w;
        acc.x += w3 * v3.x; acc.y += w3 * v3.y; acc.z += w3 * v3.z; acc.w += w3 * v3.w;
        acc.x += w4 * v4.x; acc.y += w4 * v4.y; acc.z += w4 * v4.z; acc.w += w4 * v4.w;
        acc.x += w5 * v5.x; acc.y += w5 * v5.y; acc.z += w5 * v5.z; acc.w += w5 * v5.w;
        acc.x += w6 * v6.x; acc.y += w6 * v6.y; acc.z += w6 * v6.z; acc.w += w6 * v6.w;
        acc.x += w7 * v7.x; acc.y += w7 * v7.y; acc.z += w7 * v7.z; acc.w += w7 * v7.w;
    }

    // merge the two half-warp partials (lane hl and hl+16 hold the same
    // embedding components for disjoint neighbor subsets)
    acc.x += __shfl_xor_sync(0xFFFFFFFFu, acc.x, 16);
    acc.y += __shfl_xor_sync(0xFFFFFFFFu, acc.y, 16);
    acc.z += __shfl_xor_sync(0xFFFFFFFFu, acc.z, 16);
    acc.w += __shfl_xor_sync(0xFFFFFFFFu, acc.w, 16);

    if (half == 0) {
        float4* __restrict__ o4 = reinterpret_cast<float4*>(out);
        o4[(size_t)warp_id * (EMB/4) + hl] = acc;
    }
}

extern "C" void kernel_launch(void* const* d_in, const int* in_sizes, int n_in,
                              void* d_out, int out_size)
{
    const float* emb = (const float*)d_in[0];   // [N, 64]
    const float* wei = (const float*)d_in[1];   // [N, 32]
    const int*   nei = (const int*)d_in[2];     // [N, 32] int32
    float*       out = (float*)d_out;           // [N, 1, 64]

    const int n_nodes = in_sizes[1] / TOPK;     // 200000

    const int threads = 256;                    // 8 warps/block
    const int warps_per_block = threads / 32;
    const int blocks = (n_nodes + warps_per_block - 1) / warps_per_block;

    pprgo_kernel<<<blocks, threads>>>(emb, wei, nei, out, n_nodes);
}